// round 2
// baseline (speedup 1.0000x reference)
#include <cuda_runtime.h>
#include <cstdint>

// GaussianVoxel fused: all 4 levels [16,17,zr,64,64] (zr in {1,2,4,64}) written
// by ONE kernel over the flat concatenated output. Z_COEFFS = (1,1,1,13),
// PAD=6, PATCH=13, SIZE=64, Z_MAX=64.
//
// Each thread writes 8 consecutive floats (two float4 streaming stores).
// Pure store-bound kernel: ~316 MB stores, inputs fully L1-resident.

#define BATCH 16
#define JOINTS 17
#define NBJ (BATCH * JOINTS)   // 272
#define SIZE 64
#define PADC 6
#define PATCH 13

// per-level thread counts (8 floats per thread)
#define T0 (NBJ * 1  * SIZE * (SIZE / 8))   // 139264
#define T1 (NBJ * 2  * SIZE * (SIZE / 8))   // 278528
#define T2 (NBJ * 4  * SIZE * (SIZE / 8))   // 557056
#define T3 (NBJ * 64 * SIZE * (SIZE / 8))   // 8912896
#define C0 (T0)            // 139264
#define C1 (C0 + T1)       // 417792
#define C2 (C1 + T2)       // 974848
#define TOT (C2 + T3)      // 9887744 = 38624 * 256 exactly

template<int ZRES, int ZC>
__device__ __forceinline__ void do_level(int lidx,
                                         const float* __restrict__ coords,
                                         const float* __restrict__ g,
                                         float4* __restrict__ out)
{
    // lidx = ((bj*ZRES + z)*64 + y)*8 + x8
    int x8 = lidx & 7;
    int t  = lidx >> 3;
    int y  = t & 63;
    t >>= 6;
    int z, bj;
    if (ZRES == 1) { z = 0; bj = t; }
    else           { z = t & (ZRES - 1);
                     bj = t >> (ZRES == 2 ? 1 : (ZRES == 4 ? 2 : 6)); }

    // coords table: 3.3 KB, L1-resident
    float cx = __ldg(&coords[bj * 3 + 0]);
    float cy = __ldg(&coords[bj * 3 + 1]);
    float cz = __ldg(&coords[bj * 3 + 2]);
    int xi = (int)cx;
    int yi = (int)cy;
    // zidx = ceil(cz * ZRES / 64) - 1  (cz integer-valued 0..63, exact in fp32)
    int zidx = (int)ceilf(cz * ((float)ZRES * (1.0f / 64.0f))) - 1;

    constexpr int ZPAD = ZC / 2;
    int gz = z - zidx + ZPAD;
    int gy = y - yi + PADC;

    float4 v0 = make_float4(0.f, 0.f, 0.f, 0.f);
    float4 v1 = make_float4(0.f, 0.f, 0.f, 0.f);
    if ((unsigned)gz < (unsigned)ZC && (unsigned)gy < (unsigned)PATCH) {
        const float* gp = g + (gz * PATCH + gy) * PATCH;
        int x0 = x8 * 8;
        float r[8];
        #pragma unroll
        for (int k = 0; k < 8; k++) {
            int gx = x0 + k - xi + PADC;
            r[k] = ((unsigned)gx < (unsigned)PATCH) ? __ldg(&gp[gx]) : 0.f;
        }
        v0 = make_float4(r[0], r[1], r[2], r[3]);
        v1 = make_float4(r[4], r[5], r[6], r[7]);
    }
    // streaming stores: 316 MB output >> L2, don't pollute
    __stcs(&out[lidx * 2 + 0], v0);
    __stcs(&out[lidx * 2 + 1], v1);
}

__global__ __launch_bounds__(256)
void gv_fused_kernel(const float* __restrict__ coords,
                     const float* __restrict__ g0,
                     const float* __restrict__ g1,
                     const float* __restrict__ g2,
                     const float* __restrict__ g3,
                     float4* __restrict__ out)
{
    int idx = blockIdx.x * blockDim.x + threadIdx.x;  // exact grid, no bounds check

    // float4 offsets of each level in the flat output
    constexpr int O1 = T0 * 2;            // level0 = T0 threads * 2 float4
    constexpr int O2 = O1 + T1 * 2;
    constexpr int O3 = O2 + T2 * 2;

    if (idx >= C2) {
        do_level<64, 13>(idx - C2, coords, g3, out + O3);
    } else if (idx < C0) {
        do_level<1, 1>(idx, coords, g0, out);
    } else if (idx < C1) {
        do_level<2, 1>(idx - C0, coords, g1, out + O1);
    } else {
        do_level<4, 1>(idx - C1, coords, g2, out + O2);
    }
}

extern "C" void kernel_launch(void* const* d_in, const int* in_sizes, int n_in,
                              void* d_out, int out_size)
{
    const float* coords = (const float*)d_in[0];
    const float* g0 = (const float*)d_in[1];
    const float* g1 = (const float*)d_in[2];
    const float* g2 = (const float*)d_in[3];
    const float* g3 = (const float*)d_in[4];

    gv_fused_kernel<<<TOT / 256, 256>>>(coords, g0, g1, g2, g3, (float4*)d_out);
}

// round 3
// speedup vs baseline: 1.7034x; 1.7034x over previous
#include <cuda_runtime.h>
#include <cstdint>

// GaussianVoxel fused: all 4 levels [16,17,zr,64,64] (zr in {1,2,4,64}) written
// by ONE kernel over the flat concatenated output. Z_COEFFS = (1,1,1,13),
// PAD=6, PATCH=13, SIZE=64, Z_MAX=64.
//
// One float4 per thread, lane-contiguous (each warp STG.128 = 4 full 128B
// lines). Pure store-bound: ~316 MB streaming stores, inputs L1-resident.

#define BATCH 16
#define JOINTS 17
#define NBJ (BATCH * JOINTS)   // 272
#define SIZE 64
#define PADC 6
#define PATCH 13

// per-level float4 counts
#define F0 (NBJ * 1  * SIZE * (SIZE / 4))   // 278528
#define F1 (NBJ * 2  * SIZE * (SIZE / 4))   // 557056
#define F2 (NBJ * 4  * SIZE * (SIZE / 4))   // 1114112
#define F3 (NBJ * 64 * SIZE * (SIZE / 4))   // 17825792
#define C0 (F0)            // 278528
#define C1 (C0 + F1)       // 835584
#define C2 (C1 + F2)       // 1949696
#define TOT (C2 + F3)      // 19775488 = 77248 * 256 exactly

template<int ZRES, int ZC>
__device__ __forceinline__ void do_level(int lidx,
                                         const float* __restrict__ coords,
                                         const float* __restrict__ g,
                                         float4* __restrict__ out)
{
    // lidx = ((bj*ZRES + z)*64 + y)*16 + x4
    int x4 = lidx & 15;
    int t  = lidx >> 4;
    int y  = t & 63;
    t >>= 6;
    int z, bj;
    if (ZRES == 1) { z = 0; bj = t; }
    else           { z = t & (ZRES - 1);
                     bj = t >> (ZRES == 2 ? 1 : (ZRES == 4 ? 2 : 6)); }

    // coords table: 3.3 KB, L1-resident
    float cx = __ldg(&coords[bj * 3 + 0]);
    float cy = __ldg(&coords[bj * 3 + 1]);
    float cz = __ldg(&coords[bj * 3 + 2]);
    int xi = (int)cx;
    int yi = (int)cy;
    // zidx = ceil(cz * ZRES / 64) - 1  (cz integer-valued 0..63, exact in fp32)
    int zidx = (int)ceilf(cz * ((float)ZRES * (1.0f / 64.0f))) - 1;

    constexpr int ZPAD = ZC / 2;
    int gz = z - zidx + ZPAD;
    int gy = y - yi + PADC;

    float4 v = make_float4(0.f, 0.f, 0.f, 0.f);
    if ((unsigned)gz < (unsigned)ZC && (unsigned)gy < (unsigned)PATCH) {
        const float* gp = g + (gz * PATCH + gy) * PATCH;
        int x0 = x4 * 4;
        float r[4];
        #pragma unroll
        for (int k = 0; k < 4; k++) {
            int gx = x0 + k - xi + PADC;
            r[k] = ((unsigned)gx < (unsigned)PATCH) ? __ldg(&gp[gx]) : 0.f;
        }
        v = make_float4(r[0], r[1], r[2], r[3]);
    }
    // streaming store: 316 MB output >> L2, don't pollute
    __stcs(&out[lidx], v);
}

__global__ __launch_bounds__(256)
void gv_fused_kernel(const float* __restrict__ coords,
                     const float* __restrict__ g0,
                     const float* __restrict__ g1,
                     const float* __restrict__ g2,
                     const float* __restrict__ g3,
                     float4* __restrict__ out)
{
    int idx = blockIdx.x * blockDim.x + threadIdx.x;  // exact grid, no bounds check

    if (idx >= C2) {
        do_level<64, 13>(idx - C2, coords, g3, out + C2);
    } else if (idx < C0) {
        do_level<1, 1>(idx, coords, g0, out);
    } else if (idx < C1) {
        do_level<2, 1>(idx - C0, coords, g1, out + C0);
    } else {
        do_level<4, 1>(idx - C1, coords, g2, out + C1);
    }
}

extern "C" void kernel_launch(void* const* d_in, const int* in_sizes, int n_in,
                              void* d_out, int out_size)
{
    const float* coords = (const float*)d_in[0];
    const float* g0 = (const float*)d_in[1];
    const float* g1 = (const float*)d_in[2];
    const float* g2 = (const float*)d_in[3];
    const float* g3 = (const float*)d_in[4];

    gv_fused_kernel<<<TOT / 256, 256>>>(coords, g0, g1, g2, g3, (float4*)d_out);
}